// round 3
// baseline (speedup 1.0000x reference)
#include <cuda_runtime.h>
#include <cuda_bf16.h>

// Dataset constants: N_NODES = 1e6, N_EDGES = 32e6 (edge_index is int32 —
// JAX with x64 disabled silently downcasts int64).
#define MAX_NODES   1000000
#define MAX_EDGES   32000000
#define NBUCKETS    256        // bucket = src >> 12
#define BUCKET_SH   12
#define BUCKET_NODES 4096      // 16KB of floats per bucket -> SMEM resident
#define CHUNK       16384      // edges per partition chunk
#define MAX_CHUNKS  2560
#define PART_THREADS 512
#define EPT         (CHUNK / PART_THREADS)   // 32 edges per thread
#define SUBS        8          // CTAs per bucket in the SpMV pass

// -------------------- static scratch (allocation-free rule) ----------------
__device__ unsigned int g_records[MAX_EDGES];                    // 128 MB
__device__ int   g_dir[MAX_CHUNKS * (NBUCKETS + 1)];             // ~2.6 MB
__device__ float g_agg1[MAX_NODES];
__device__ float g_h1[MAX_NODES];
__device__ float g_agg2[MAX_NODES];

// ---------------------------------------------------------------------------
// zero both aggregation buffers
// ---------------------------------------------------------------------------
__global__ void zero_kernel(int n) {
    int i = blockIdx.x * blockDim.x + threadIdx.x;
    int stride = gridDim.x * blockDim.x;
    for (; i < n; i += stride) {
        g_agg1[i] = 0.0f;
        g_agg2[i] = 0.0f;
    }
}

// ---------------------------------------------------------------------------
// Partition: group each chunk's edges by src-bucket into g_records,
// fully staged through SMEM so every global write is coalesced.
// Record = (src & 0xFFF) << 20 | dst   (dst < 2^20)
// dir[c][b] = absolute start offset of bucket b inside chunk c.
// ---------------------------------------------------------------------------
extern __shared__ unsigned int s_raw[];

__global__ __launch_bounds__(PART_THREADS, 2)
void partition_kernel(const int* __restrict__ src,
                      const int* __restrict__ dst,
                      int n_edges) {
    // SMEM carve
    unsigned int* buf    = s_raw;                       // CHUNK uints (64 KB)
    int* warp_hist       = (int*)(buf + CHUNK);         // 16*256 ints (16 KB)
    int* hist            = warp_hist + 16 * NBUCKETS;   // 256
    int* offs            = hist + NBUCKETS;             // 257
    int* cursor          = offs + NBUCKETS + 1;         // 256
    int* wsum            = cursor + NBUCKETS;           // 8 (warp scan temps)

    const int c    = blockIdx.x;
    const int base = c * CHUNK;
    const int cnt  = min(CHUNK, n_edges - base);
    const int tid  = threadIdx.x;
    const int wid  = tid >> 5;
    const int lane = tid & 31;

    // clear per-warp hists
    for (int i = tid; i < 16 * NBUCKETS; i += PART_THREADS) warp_hist[i] = 0;
    __syncthreads();

    // Phase A: histogram src buckets (per-warp private hist to cut conflicts)
    int* myhist = warp_hist + wid * NBUCKETS;
    for (int k = 0; k < EPT; k++) {
        int e = k * PART_THREADS + tid;
        if (e < cnt) {
            int s = src[base + e];
            atomicAdd(&myhist[s >> BUCKET_SH], 1);
        }
    }
    __syncthreads();

    // reduce per-warp hists
    if (tid < NBUCKETS) {
        int sum = 0;
#pragma unroll
        for (int w = 0; w < 16; w++) sum += warp_hist[w * NBUCKETS + tid];
        hist[tid] = sum;
    }
    __syncthreads();

    // exclusive prefix over 256 bins (8-warp scan)
    if (tid < NBUCKETS) {
        int v = hist[tid];
        int inc = v;
#pragma unroll
        for (int d = 1; d < 32; d <<= 1) {
            int n = __shfl_up_sync(0xFFFFFFFF, inc, d);
            if (lane >= d) inc += n;
        }
        if (lane == 31) wsum[tid >> 5] = inc;
        offs[tid] = inc - v;  // exclusive within warp
    }
    __syncthreads();
    if (tid < NBUCKETS) {
        int add = 0;
#pragma unroll
        for (int w = 0; w < 8; w++)
            if (w < (tid >> 5)) add += wsum[w];
        offs[tid] += add;
        cursor[tid] = offs[tid];
        // write directory (absolute offsets)
        g_dir[c * (NBUCKETS + 1) + tid] = base + offs[tid];
    }
    if (tid == 0) g_dir[c * (NBUCKETS + 1) + NBUCKETS] = base + cnt;
    __syncthreads();

    // Phase B: place packed records into SMEM buf at bucket-local offsets
    for (int k = 0; k < EPT; k++) {
        int e = k * PART_THREADS + tid;
        if (e < cnt) {
            int s = src[base + e];
            int d = dst[base + e];
            int pos = atomicAdd(&cursor[s >> BUCKET_SH], 1);
            buf[pos] = ((unsigned int)(s & 0xFFF) << 20) | (unsigned int)d;
        }
    }
    __syncthreads();

    // coalesced copy out
    for (int i = tid; i < cnt; i += PART_THREADS)
        g_records[base + i] = buf[i];
}

// ---------------------------------------------------------------------------
// SpMV pass: for bucket b, load vals[b*4096 .. +4096) into SMEM, then walk
// every chunk's bucket-b record range: v = smem_x[src_low]; RED(out[dst], v).
// Record reads are coalesced; the gather is an LDS; only the RED is random.
// ---------------------------------------------------------------------------
__global__ __launch_bounds__(256)
void spmv_kernel(const float* __restrict__ vals,
                 float* __restrict__ out_agg,
                 int n_nodes, int n_chunks) {
    __shared__ float sx[BUCKET_NODES];

    const int b   = blockIdx.x / SUBS;
    const int sub = blockIdx.x % SUBS;
    const int tid = threadIdx.x;
    const int wid = tid >> 5;
    const int lane = tid & 31;

    // load x-slice for this bucket
    const int node0 = b * BUCKET_NODES;
    for (int i = tid; i < BUCKET_NODES; i += 256) {
        int n = node0 + i;
        sx[i] = (n < n_nodes) ? __ldg(&vals[n]) : 0.0f;
    }
    __syncthreads();

    // each warp walks a strided set of chunks
    const int worker  = sub * 8 + wid;          // 0 .. SUBS*8-1
    const int nworker = SUBS * 8;
    for (int c = worker; c < n_chunks; c += nworker) {
        const int* dirrow = &g_dir[c * (NBUCKETS + 1)];
        int lo = __ldg(&dirrow[b]);
        int hi = __ldg(&dirrow[b + 1]);
        for (int i = lo + lane; i < hi; i += 32) {
            unsigned int rec = g_records[i];
            float v = sx[rec >> 20];
            atomicAdd(&out_agg[rec & 0xFFFFF], v);
        }
    }
}

// ---------------------------------------------------------------------------
// per-node preactivation for pass 2: h1 = relu(agg1 * w1)  (node-side, 1M ops
// instead of edge-side 32M)
// ---------------------------------------------------------------------------
__global__ void prelu_kernel(const float* __restrict__ w1ptr, int n) {
    const float w1 = __ldg(w1ptr);
    int i = blockIdx.x * blockDim.x + threadIdx.x;
    int stride = gridDim.x * blockDim.x;
    for (; i < n; i += stride)
        g_h1[i] = fmaxf(g_agg1[i] * w1, 0.0f);
}

// ---------------------------------------------------------------------------
// epilogue: out = sigmoid(relu(agg2 * w2))
// ---------------------------------------------------------------------------
__global__ void epilogue_kernel(const float* __restrict__ w2ptr,
                                float* __restrict__ out, int n) {
    const float w2 = __ldg(w2ptr);
    int i = blockIdx.x * blockDim.x + threadIdx.x;
    int stride = gridDim.x * blockDim.x;
    for (; i < n; i += stride) {
        float h = fmaxf(g_agg2[i] * w2, 0.0f);
        out[i] = 1.0f / (1.0f + __expf(-h));
    }
}

// ---------------------------------------------------------------------------
// kernel_launch: 6 graph-capturable launches, allocation-free.
// Inputs: x [N,1] f32, edge_index [2,E] int32, w1 [1,1] f32, w2 [1,1] f32
// ---------------------------------------------------------------------------
extern "C" void kernel_launch(void* const* d_in, const int* in_sizes, int n_in,
                              void* d_out, int out_size) {
    const float* x  = (const float*)d_in[0];
    const int* ei   = (const int*)d_in[1];
    const float* w1 = (const float*)d_in[2];
    const float* w2 = (const float*)d_in[3];
    float* out = (float*)d_out;

    const int n_nodes = in_sizes[0];
    const int n_edges = in_sizes[1] / 2;
    const int* src = ei;
    const int* dst = ei + n_edges;

    int n_chunks = (n_edges + CHUNK - 1) / CHUNK;
    if (n_chunks > MAX_CHUNKS) n_chunks = MAX_CHUNKS;  // safety (dataset: 1954)

    float* agg1; float* agg2; float* h1;
    cudaGetSymbolAddress((void**)&agg1, g_agg1);
    cudaGetSymbolAddress((void**)&agg2, g_agg2);
    cudaGetSymbolAddress((void**)&h1,   g_h1);

    // partition kernel needs ~84KB dynamic SMEM
    const int part_smem = CHUNK * 4 + 16 * NBUCKETS * 4 +
                          (NBUCKETS + (NBUCKETS + 1) + NBUCKETS + 8) * 4;
    static bool attr_done = false;
    if (!attr_done) {
        cudaFuncSetAttribute(partition_kernel,
                             cudaFuncAttributeMaxDynamicSharedMemorySize,
                             part_smem);
        attr_done = true;
    }

    // 1) zero aggregation buffers
    zero_kernel<<<2048, 256>>>(n_nodes);

    // 2) partition edges by src-bucket (records reused by both passes)
    partition_kernel<<<n_chunks, PART_THREADS, part_smem>>>(src, dst, n_edges);

    // 3) pass 1: agg1[dst] += x[src]
    spmv_kernel<<<NBUCKETS * SUBS, 256>>>(x, agg1, n_nodes, n_chunks);

    // 4) h1 = relu(agg1 * w1)
    prelu_kernel<<<2048, 256>>>(w1, n_nodes);

    // 5) pass 2: agg2[dst] += h1[src]
    spmv_kernel<<<NBUCKETS * SUBS, 256>>>(h1, agg2, n_nodes, n_chunks);

    // 6) epilogue
    {
        int eblocks = (n_nodes + 255) / 256;
        if (eblocks > 4096) eblocks = 4096;
        epilogue_kernel<<<eblocks, 256>>>(w2, out, n_nodes);
    }
}

// round 4
// speedup vs baseline: 1.1174x; 1.1174x over previous
#include <cuda_runtime.h>
#include <cuda_bf16.h>

// Dataset: N_NODES = 1e6, N_EDGES = 32e6, edge_index int32 (JAX x64-off downcast).
#define MAX_NODES    1000000
#define MAX_EDGES    32000000
#define BUCKET_SH    12
#define BUCKET_NODES 4096
#define NBUCKETS     245            // ceil(1e6 / 4096); dst>>12 in [0,244]
#define NBPAD        256
#define CHUNK        4096
#define MAX_CHUNKS   7840           // >= ceil(32e6/4096)=7813
#define SUBS         4              // CTAs per bucket in spmv
#define THREADS      256

// ----------------------- static device scratch -----------------------------
__device__ unsigned int g_records[MAX_EDGES];            // 128 MB: (dst&0xFFF)<<20 | src
__device__ int   g_dir  [NBPAD * MAX_CHUNKS];            // [b][c] per-chunk counts
__device__ int   g_start[NBPAD * MAX_CHUNKS];            // [b][c] absolute placement start
__device__ int   g_total[NBPAD];
__device__ int   g_bbase[NBPAD + 1];
__device__ float g_agg1[MAX_NODES];
__device__ float g_agg2[MAX_NODES];

// --------------------------- helpers ---------------------------------------
// 256-thread exclusive scan. s_w must have >= 9 ints. Returns exclusive prefix;
// s_w[8] holds the block total after the final __syncthreads inside.
__device__ __forceinline__ int block_excl_scan(int v, int* s_w) {
    int lane = threadIdx.x & 31;
    int wid  = threadIdx.x >> 5;
    int inc = v;
#pragma unroll
    for (int d = 1; d < 32; d <<= 1) {
        int n = __shfl_up_sync(0xFFFFFFFF, inc, d);
        if (lane >= d) inc += n;
    }
    if (lane == 31) s_w[wid] = inc;
    __syncthreads();
    if (wid == 0 && lane < 8) {
        int x = s_w[lane];
        int p = x;
#pragma unroll
        for (int d = 1; d < 8; d <<= 1) {
            int n = __shfl_up_sync(0xFF, p, d);
            if (lane >= d) p += n;
        }
        s_w[lane] = p - x;          // exclusive warp offsets
        if (lane == 7) s_w[8] = p;  // block total
    }
    __syncthreads();
    return inc - v + s_w[wid];
}

// ---------------------------------------------------------------------------
__global__ void zero_kernel(int n) {
    int i = blockIdx.x * blockDim.x + threadIdx.x;
    int stride = gridDim.x * blockDim.x;
    for (; i < n; i += stride) {
        g_agg1[i] = 0.0f;
        g_agg2[i] = 0.0f;
    }
}

// K1: per-chunk histogram of dst buckets -> g_dir[b][c]
__global__ __launch_bounds__(THREADS)
void hist_kernel(const int* __restrict__ dst, int n_edges) {
    __shared__ int wh[8 * NBPAD];
    const int c    = blockIdx.x;
    const int base = c * CHUNK;
    const int cnt  = min(CHUNK, n_edges - base);
    const int tid  = threadIdx.x;
    for (int i = tid; i < 8 * NBPAD; i += THREADS) wh[i] = 0;
    __syncthreads();
    int* myh = wh + (tid >> 5) * NBPAD;
    for (int e = tid; e < cnt; e += THREADS)
        atomicAdd(&myh[dst[base + e] >> BUCKET_SH], 1);
    __syncthreads();
    if (tid < NBPAD) {
        int s = 0;
#pragma unroll
        for (int w = 0; w < 8; w++) s += wh[w * NBPAD + tid];
        if (tid < NBUCKETS) g_dir[tid * MAX_CHUNKS + c] = s;
    }
}

// K2a: row totals
__global__ __launch_bounds__(THREADS)
void total_kernel(int n_chunks) {
    __shared__ int s_w[9];
    const int b = blockIdx.x;
    const int* row = &g_dir[b * MAX_CHUNKS];
    int s = 0;
    for (int i = threadIdx.x; i < n_chunks; i += THREADS) s += row[i];
    // reduce via scan helper (total ends in s_w[8])
    block_excl_scan(s, s_w);
    if (threadIdx.x == 0) g_total[b] = s_w[8];
}

// K2b: exclusive scan over bucket totals -> g_bbase
__global__ __launch_bounds__(THREADS)
void base_scan_kernel() {
    __shared__ int s_w[9];
    int tid = threadIdx.x;
    int v = (tid < NBUCKETS) ? g_total[tid] : 0;
    int excl = block_excl_scan(v, s_w);
    g_bbase[tid] = excl;                 // for tid >= NBUCKETS this equals total
    if (tid == 0) g_bbase[NBPAD] = s_w[8];
}

// K2c: per-bucket running scan over chunks -> g_start[b][c]
__global__ __launch_bounds__(THREADS)
void start_scan_kernel(int n_chunks) {
    __shared__ int s_w[9];
    const int b = blockIdx.x;
    const int row = b * MAX_CHUNKS;
    int carry = g_bbase[b];
    for (int t0 = 0; t0 < n_chunks; t0 += THREADS) {
        int idx = t0 + threadIdx.x;
        int v = (idx < n_chunks) ? g_dir[row + idx] : 0;
        int excl = block_excl_scan(v, s_w);
        if (idx < n_chunks) g_start[row + idx] = carry + excl;
        carry += s_w[8];
        __syncthreads();   // protect s_w before next tile
    }
}

// K3: placement — bucket each chunk's edges in SMEM, copy out to global
// contiguous bucket ranges (near-coalesced). Edges held in registers.
__global__ __launch_bounds__(THREADS)
void place_kernel(const int* __restrict__ src,
                  const int* __restrict__ dst,
                  int n_edges) {
    __shared__ unsigned int buf[CHUNK];
    __shared__ unsigned char sb[CHUNK];
    __shared__ int wh[8 * NBPAD];
    __shared__ int hist[NBPAD];
    __shared__ int offs[NBPAD];
    __shared__ int cursor[NBPAD];
    __shared__ int gst[NBPAD];
    __shared__ int s_w[9];

    const int c    = blockIdx.x;
    const int base = c * CHUNK;
    const int cnt  = min(CHUNK, n_edges - base);
    const int tid  = threadIdx.x;

    for (int i = tid; i < 8 * NBPAD; i += THREADS) wh[i] = 0;
    __syncthreads();

    unsigned int rec[16];
    int bk[16];
    int* myh = wh + (tid >> 5) * NBPAD;
#pragma unroll
    for (int k = 0; k < 16; k++) {
        int e = k * THREADS + tid;
        if (e < cnt) {
            int d = dst[base + e];
            int s = src[base + e];
            bk[k] = d >> BUCKET_SH;
            rec[k] = ((unsigned int)(d & 0xFFF) << 20) | (unsigned int)s;
            atomicAdd(&myh[bk[k]], 1);
        } else {
            bk[k] = -1;
        }
    }
    __syncthreads();

    if (tid < NBPAD) {
        int s = 0;
#pragma unroll
        for (int w = 0; w < 8; w++) s += wh[w * NBPAD + tid];
        hist[tid] = s;
    }
    __syncthreads();

    int hv = hist[tid];
    int excl = block_excl_scan(hv, s_w);
    offs[tid] = excl;
    cursor[tid] = excl;
    gst[tid] = (tid < NBUCKETS) ? g_start[tid * MAX_CHUNKS + c] : 0;
    __syncthreads();

#pragma unroll
    for (int k = 0; k < 16; k++) {
        if (bk[k] >= 0) {
            int slot = atomicAdd(&cursor[bk[k]], 1);
            buf[slot] = rec[k];
            sb[slot] = (unsigned char)bk[k];
        }
    }
    __syncthreads();

    for (int i = tid; i < cnt; i += THREADS) {
        int b = sb[i];
        g_records[gst[b] + (i - offs[b])] = buf[i];
    }
}

// K4/K5: SpMV over globally-contiguous bucket ranges; SMEM accumulation.
template <bool RELU_W>
__global__ __launch_bounds__(THREADS)
void spmv_kernel(const float* __restrict__ vals,
                 const float* __restrict__ wptr,
                 float* __restrict__ agg,
                 int n_nodes) {
    __shared__ float acc[BUCKET_NODES];
    const int b   = blockIdx.x / SUBS;
    const int sub = blockIdx.x % SUBS;
    const int tid = threadIdx.x;
    const float w = RELU_W ? __ldg(wptr) : 0.0f;

    for (int j = tid; j < BUCKET_NODES; j += THREADS) acc[j] = 0.0f;
    __syncthreads();

    const int lo  = g_bbase[b];
    const int hi  = g_bbase[b + 1];
    const int len = hi - lo;
    const int q0  = lo + (int)(((long long)len * sub) / SUBS);
    const int q1  = lo + (int)(((long long)len * (sub + 1)) / SUBS);

    int i = q0 + tid;
    for (; i + 3 * THREADS < q1; i += 4 * THREADS) {
        unsigned int r0 = g_records[i];
        unsigned int r1 = g_records[i + THREADS];
        unsigned int r2 = g_records[i + 2 * THREADS];
        unsigned int r3 = g_records[i + 3 * THREADS];
        float v0 = __ldg(&vals[r0 & 0xFFFFF]);
        float v1 = __ldg(&vals[r1 & 0xFFFFF]);
        float v2 = __ldg(&vals[r2 & 0xFFFFF]);
        float v3 = __ldg(&vals[r3 & 0xFFFFF]);
        if (RELU_W) {
            v0 = fmaxf(v0 * w, 0.0f);
            v1 = fmaxf(v1 * w, 0.0f);
            v2 = fmaxf(v2 * w, 0.0f);
            v3 = fmaxf(v3 * w, 0.0f);
        }
        atomicAdd(&acc[r0 >> 20], v0);
        atomicAdd(&acc[r1 >> 20], v1);
        atomicAdd(&acc[r2 >> 20], v2);
        atomicAdd(&acc[r3 >> 20], v3);
    }
    for (; i < q1; i += THREADS) {
        unsigned int r = g_records[i];
        float v = __ldg(&vals[r & 0xFFFFF]);
        if (RELU_W) v = fmaxf(v * w, 0.0f);
        atomicAdd(&acc[r >> 20], v);
    }
    __syncthreads();

    const int node0 = b * BUCKET_NODES;
    for (int j = tid; j < BUCKET_NODES; j += THREADS) {
        int n = node0 + j;
        if (n < n_nodes) {
            float v = acc[j];
            if (v != 0.0f) atomicAdd(&agg[n], v);
        }
    }
}

// K6: epilogue out = sigmoid(relu(agg2 * w2))
__global__ void epilogue_kernel(const float* __restrict__ w2ptr,
                                float* __restrict__ out, int n) {
    const float w2 = __ldg(w2ptr);
    int i = blockIdx.x * blockDim.x + threadIdx.x;
    int stride = gridDim.x * blockDim.x;
    for (; i < n; i += stride) {
        float h = fmaxf(g_agg2[i] * w2, 0.0f);
        out[i] = 1.0f / (1.0f + __expf(-h));
    }
}

// ---------------------------------------------------------------------------
extern "C" void kernel_launch(void* const* d_in, const int* in_sizes, int n_in,
                              void* d_out, int out_size) {
    const float* x  = (const float*)d_in[0];
    const int* ei   = (const int*)d_in[1];
    const float* w1 = (const float*)d_in[2];
    const float* w2 = (const float*)d_in[3];
    float* out = (float*)d_out;

    const int n_nodes = in_sizes[0];
    const int n_edges = in_sizes[1] / 2;
    const int* src = ei;
    const int* dst = ei + n_edges;

    int n_chunks = (n_edges + CHUNK - 1) / CHUNK;
    if (n_chunks > MAX_CHUNKS) n_chunks = MAX_CHUNKS;

    float* agg1; float* agg2;
    cudaGetSymbolAddress((void**)&agg1, g_agg1);
    cudaGetSymbolAddress((void**)&agg2, g_agg2);

    // 1) zero aggregation buffers
    zero_kernel<<<2048, THREADS>>>(n_nodes);
    // 2) histogram per chunk
    hist_kernel<<<n_chunks, THREADS>>>(dst, n_edges);
    // 3) bucket totals, 4) bucket bases, 5) per-(bucket,chunk) starts
    total_kernel<<<NBUCKETS, THREADS>>>(n_chunks);
    base_scan_kernel<<<1, THREADS>>>();
    start_scan_kernel<<<NBUCKETS, THREADS>>>(n_chunks);
    // 6) placement (counting sort by dst bucket)
    place_kernel<<<n_chunks, THREADS>>>(src, dst, n_edges);
    // 7) pass 1: agg1 += scatter(x)
    spmv_kernel<false><<<NBUCKETS * SUBS, THREADS>>>(x, w1, agg1, n_nodes);
    // 8) pass 2: agg2 += scatter(relu(agg1 * w1))   (relu fused into gather)
    spmv_kernel<true><<<NBUCKETS * SUBS, THREADS>>>(agg1, w1, agg2, n_nodes);
    // 9) epilogue
    {
        int eblocks = (n_nodes + THREADS - 1) / THREADS;
        if (eblocks > 4096) eblocks = 4096;
        epilogue_kernel<<<eblocks, THREADS>>>(w2, out, n_nodes);
    }
}

// round 5
// speedup vs baseline: 1.2764x; 1.1423x over previous
#include <cuda_runtime.h>
#include <cuda_bf16.h>

// Dataset: N_NODES = 1e6, N_EDGES = 32e6, edge_index int32 (JAX x64-off downcast).
#define MAX_NODES 1000000

__device__ float g_agg1[MAX_NODES];
__device__ float g_agg2[MAX_NODES];

// ---------------------------------------------------------------------------
// zero both aggregation buffers, vectorized
// ---------------------------------------------------------------------------
__global__ void zero_kernel(int n) {
    int i = blockIdx.x * blockDim.x + threadIdx.x;
    int stride = gridDim.x * blockDim.x;
    float4* a1 = reinterpret_cast<float4*>(g_agg1);
    float4* a2 = reinterpret_cast<float4*>(g_agg2);
    int n4 = n >> 2;
    for (int j = i; j < n4; j += stride) {
        a1[j] = make_float4(0.f, 0.f, 0.f, 0.f);
        a2[j] = make_float4(0.f, 0.f, 0.f, 0.f);
    }
    for (int j = (n4 << 2) + i; j < n; j += stride) {
        g_agg1[j] = 0.0f;
        g_agg2[j] = 0.0f;
    }
}

// ---------------------------------------------------------------------------
// Scatter-add pass, 8 edges per thread per iteration (2x int4 per side).
//   RELU_W == false: agg[dst] += vals[src]
//   RELU_W == true : agg[dst] += max(vals[src]*w, 0)
// Random gathers use __ldcg (L2-only; x/agg are L2-resident, L1 is useless).
// atomicAdd with unused result compiles to REDG (no return trip).
// ---------------------------------------------------------------------------
template <bool RELU_W>
__global__ __launch_bounds__(256)
void scatter_kernel(const int* __restrict__ src,
                    const int* __restrict__ dst,
                    const float* __restrict__ vals,
                    const float* __restrict__ wptr,
                    float* __restrict__ agg,
                    int n_edges) {
    const float w = RELU_W ? __ldg(wptr) : 0.0f;

    int tid = blockIdx.x * blockDim.x + threadIdx.x;
    int stride = gridDim.x * blockDim.x;

    const int4* src4 = reinterpret_cast<const int4*>(src);
    const int4* dst4 = reinterpret_cast<const int4*>(dst);

    int n_oct = n_edges >> 3;  // groups of 8 edges
    for (int i = tid; i < n_oct; i += stride) {
        int4 sa = src4[2 * i];
        int4 sb = src4[2 * i + 1];
        int4 da = dst4[2 * i];
        int4 db = dst4[2 * i + 1];

        int s[8] = {sa.x, sa.y, sa.z, sa.w, sb.x, sb.y, sb.z, sb.w};
        int d[8] = {da.x, da.y, da.z, da.w, db.x, db.y, db.z, db.w};

        float v[8];
#pragma unroll
        for (int k = 0; k < 8; k++) {
            float t = __ldcg(&vals[s[k]]);
            if (RELU_W) t = fmaxf(t * w, 0.0f);
            v[k] = t;
        }
#pragma unroll
        for (int k = 0; k < 8; k++) {
            atomicAdd(&agg[d[k]], v[k]);
        }
    }

    // tail
    for (int e = (n_oct << 3) + tid; e < n_edges; e += stride) {
        int s = src[e];
        int d = dst[e];
        float t = __ldcg(&vals[s]);
        if (RELU_W) t = fmaxf(t * w, 0.0f);
        atomicAdd(&agg[d], t);
    }
}

// ---------------------------------------------------------------------------
// epilogue: out = sigmoid(relu(agg2 * w2))
// ---------------------------------------------------------------------------
__global__ void epilogue_kernel(const float* __restrict__ w2ptr,
                                float* __restrict__ out, int n) {
    const float w2 = __ldg(w2ptr);
    int i = blockIdx.x * blockDim.x + threadIdx.x;
    int stride = gridDim.x * blockDim.x;
    for (; i < n; i += stride) {
        float h = fmaxf(g_agg2[i] * w2, 0.0f);
        out[i] = 1.0f / (1.0f + __expf(-h));
    }
}

// ---------------------------------------------------------------------------
extern "C" void kernel_launch(void* const* d_in, const int* in_sizes, int n_in,
                              void* d_out, int out_size) {
    const float* x  = (const float*)d_in[0];
    const int* ei   = (const int*)d_in[1];
    const float* w1 = (const float*)d_in[2];
    const float* w2 = (const float*)d_in[3];
    float* out = (float*)d_out;

    const int n_nodes = in_sizes[0];
    const int n_edges = in_sizes[1] / 2;
    const int* src = ei;
    const int* dst = ei + n_edges;

    float* agg1; float* agg2;
    cudaGetSymbolAddress((void**)&agg1, g_agg1);
    cudaGetSymbolAddress((void**)&agg2, g_agg2);

    // 1) zero scratch
    zero_kernel<<<1184, 256>>>(n_nodes);

    // scatter grid: 8 edges per thread, one wave-ish sizing
    int threads = 256;
    long long want = ((long long)n_edges / 8 + threads - 1) / threads;
    int blocks = (int)(want > 1048576LL ? 1048576LL : want);
    if (blocks < 1) blocks = 1;

    // 2) pass 1: agg1[dst] += x[src]
    scatter_kernel<false><<<blocks, threads>>>(src, dst, x, w1, agg1, n_edges);

    // 3) pass 2: agg2[dst] += relu(agg1[src] * w1)
    scatter_kernel<true><<<blocks, threads>>>(src, dst, agg1, w1, agg2, n_edges);

    // 4) epilogue
    {
        int eblocks = (n_nodes + threads - 1) / threads;
        if (eblocks > 4096) eblocks = 4096;
        epilogue_kernel<<<eblocks, threads>>>(w2, out, n_nodes);
    }
}